// round 16
// baseline (speedup 1.0000x reference)
#include <cuda_runtime.h>
#include <cuda_fp16.h>
#include <math.h>
#include <cstdint>

#define BSZ 4
#define CH  128
#define HH  128
#define WW  128
#define HWP (HH*WW)

typedef unsigned long long u64;
typedef uint32_t u32;

// ================= scratch (static device memory) =================
__device__ __half g_r1 [(size_t)BSZ*HWP*CH];  // bn1 output, NHWC fp16
__device__ __half g_d1 [(size_t)BSZ*HWP*CH];  // layer1 output, NHWC fp16
// deform weights, fragment-packed fp16: [k][mi 8][ki 8][lane 32] uint4
__device__ uint4 g_wF1[9*8*8*32];
__device__ uint4 g_wF2[9*8*8*32];
// offmod weights (27 rows padded to 32): [k][mi 2][ki 8][lane 32] uint4
__device__ uint4 g_oF1[9*2*8*32];
__device__ uint4 g_oF2[9*2*8*32];

// ================= helpers =================
__device__ __forceinline__ u32 smem_to_u32(const void* p){
    u32 a; asm("{ .reg .u64 t; cvta.to.shared.u64 t, %1; cvt.u32.u64 %0, t; }" : "=r"(a) : "l"(p));
    return a;
}
__device__ __forceinline__ u32 pack_h2(float a, float b){
    __half2 h = __floats2half2_rn(a, b);
    return *(u32*)&h;
}
__device__ __forceinline__ void mma_f16(float* d, const u32* a, u32 b0, u32 b1){
    asm volatile(
        "mma.sync.aligned.m16n8k16.row.col.f32.f16.f16.f32 "
        "{%0,%1,%2,%3}, {%4,%5,%6,%7}, {%8,%9}, {%0,%1,%2,%3};"
        : "+f"(d[0]), "+f"(d[1]), "+f"(d[2]), "+f"(d[3])
        : "r"(a[0]), "r"(a[1]), "r"(a[2]), "r"(a[3]), "r"(b0), "r"(b1));
}
// non-trans: cols smem is px-major (already B^T) -> direct col-major B fragment
__device__ __forceinline__ void ldmx4(u32* r, u32 addr){
    asm volatile("ldmatrix.sync.aligned.m8n8.x4.shared.b16 {%0,%1,%2,%3}, [%4];"
        : "=r"(r[0]), "=r"(r[1]), "=r"(r[2]), "=r"(r[3]) : "r"(addr));
}

#define ROWB 272
#define BUFB (64*ROWB)        // 17408 bytes per cols buffer (fp16)

// phase-A patch: [row 3][px 66][272B] fp16
#define OPX_STRIDE 272
#define OROW_STRIDE (66*OPX_STRIDE)      // 17952
#define OPATCH_BYTES (3*OROW_STRIDE)     // 53856
// s_offm lives above the union of (patch, cols double buffer)
#define SOFFM_OFF 53856                   // 27*64 floats = 6912 B
#define FUSED_SMEM (SOFFM_OFF + 6912)     // 60768

// ================= prep: all weights -> fragment order, fp16 ================
__global__ void prep_all_kernel(const float* __restrict__ w1, const float* __restrict__ w2,
                                const float* __restrict__ o1w, const float* __restrict__ m1w,
                                const float* __restrict__ o2w, const float* __restrict__ m2w){
    int i = blockIdx.x*256 + threadIdx.x;
    if (i < 36864){
        int lane = i & 31;
        int ki   = (i>>5) & 7;
        int mi   = (i>>8) & 7;
        int rest = i >> 11;            // 0..17
        int k    = rest % 9;
        int layer= rest / 9;
        const float* w = layer ? w2 : w1;
        int r  = lane >> 2;
        int cp = (lane & 3)*2;
        int row0 = mi*16 + r;
        int col0 = ki*16 + cp;
        float v[4][2];
#pragma unroll
        for (int q = 0; q < 4; q++){
            int ro = row0 + ((q & 1) ? 8 : 0);
            int co_ = col0 + ((q >> 1) ? 8 : 0);
#pragma unroll
            for (int e = 0; e < 2; e++)
                v[q][e] = w[(ro*CH + (co_+e))*9 + k];
        }
        uint4 o;
        o.x = pack_h2(v[0][0], v[0][1]);
        o.y = pack_h2(v[1][0], v[1][1]);
        o.z = pack_h2(v[2][0], v[2][1]);
        o.w = pack_h2(v[3][0], v[3][1]);
        uint4* dst = layer ? g_wF2 : g_wF1;
        dst[((k*8 + mi)*8 + ki)*32 + lane] = o;
    } else if (i < 36864 + 9216){
        int j = i - 36864;
        int lane = j & 31;
        int ki   = (j>>5) & 7;
        int mi   = (j>>8) & 1;
        int rest = j >> 9;             // 0..17
        int k    = rest % 9;
        int layer= rest / 9;
        const float* ow = layer ? o2w : o1w;
        const float* mw = layer ? m2w : m1w;
        int r  = lane >> 2;
        int cp = (lane & 3)*2;
        int row0 = mi*16 + r;
        int col0 = ki*16 + cp;
        float v[4][2];
#pragma unroll
        for (int q = 0; q < 4; q++){
            int ro = row0 + ((q & 1) ? 8 : 0);
            int c_ = col0 + ((q >> 1) ? 8 : 0);
#pragma unroll
            for (int e = 0; e < 2; e++){
                int c = c_ + e;
                float val = 0.f;
                if (ro < 18)      val = ow[(ro*CH + c)*9 + k];
                else if (ro < 27) val = mw[((ro-18)*CH + c)*9 + k];
                v[q][e] = val;
            }
        }
        uint4 o;
        o.x = pack_h2(v[0][0], v[0][1]);
        o.y = pack_h2(v[1][0], v[1][1]);
        o.z = pack_h2(v[2][0], v[2][1]);
        o.w = pack_h2(v[3][0], v[3][1]);
        uint4* dst = layer ? g_oF2 : g_oF1;
        dst[((k*2 + mi)*8 + ki)*32 + lane] = o;
    }
}

// ================= bn1 + transpose to NHWC fp16 =================
__global__ void bn1_nhwc_kernel(const float* __restrict__ x,
                                const float* __restrict__ g, const float* __restrict__ b_,
                                const float* __restrict__ m, const float* __restrict__ v){
    __shared__ float tile[32][33];
    int bid = blockIdx.x;
    int wb = bid & 3, cb = (bid >> 2) & 3, h = (bid >> 4) & 127, b = bid >> 11;
    int tx = threadIdx.x & 31, ty = threadIdx.x >> 5;
    int c0 = cb*32, w0 = wb*32;
#pragma unroll
    for (int i = 0; i < 4; i++){
        int c = c0 + ty + i*8;
        float s  = g[c] * rsqrtf(v[c] + 1e-5f);
        float bb = b_[c] - m[c]*s;
        float xv = x[((size_t)(b*CH + c))*HWP + h*WW + w0 + tx];
        tile[ty + i*8][tx] = xv*s + bb;
    }
    __syncthreads();
#pragma unroll
    for (int i = 0; i < 4; i++){
        int w = w0 + ty + i*8;
        g_r1[(((size_t)b*HWP) + h*WW + w)*CH + c0 + tx] = __float2half(tile[tx][ty + i*8]);
    }
}

// ================= fused offmod + deformable conv =================
// grid 1024 = b*h*2half; block 256 (8 warps); tile 64px x 128co.
// Phase A: dense 3x3 conv (27 ch) on the 3x66 patch -> s_offm[27][64] in smem.
// Phase B: deformable conv, corners from s_offm, fp16 HFMA2 bilinear blend.
// MODE 0: out = prelu(conv) -> NHWC fp16 d1 (p0 = alpha)
// MODE 1: out = bn2(conv) + x -> CHW fp32 d_out (p0 = x CHW)
template<int MODE>
__global__ void __launch_bounds__(256,2)
fused_layer_kernel(const __half* __restrict__ src,
                   const uint4* __restrict__ oF,
                   const float* __restrict__ offb, const float* __restrict__ modb,
                   const uint4* __restrict__ wF,
                   const float* __restrict__ p0,
                   const float* __restrict__ bn_g, const float* __restrict__ bn_b,
                   const float* __restrict__ bn_m, const float* __restrict__ bn_v,
                   void* __restrict__ out_){
    extern __shared__ __align__(16) char dsm[];
    float* s_offm = (float*)(dsm + SOFFM_OFF);   // [27][64]

    int t = threadIdx.x, lane = t & 31, wid = t >> 5;
    int b = blockIdx.x >> 8, rem = blockIdx.x & 255;
    int h = rem >> 1, w0 = (rem & 1) << 6;

    int sub  = lane & 7;
    int grp  = lane >> 3;
    int lrow = ((grp >> 1) << 3) + sub;
    int lcoff= (grp & 1) << 4;
    int rfrag = lane >> 2;
    int cfrag = (lane & 3)*2;

    u32 smb = smem_to_u32(dsm);
    const __half* srcb = src + (size_t)b*HWP*CH;

    // ================= PHASE A: offset/mask conv =================
    {
        // copy 3x66 fp16 patch
        for (int i = t; i < 198*16; i += 256){
            int pair = i >> 4;
            int s16  = i & 15;
            int row  = pair / 66;
            int px   = pair - row*66;
            int y = h - 1 + row;
            int x = w0 - 1 + px;
            bool ok = ((unsigned)y < HH) && ((unsigned)x < WW);
            uint4 val = make_uint4(0,0,0,0);
            if (ok) val = ((const uint4*)(srcb + ((size_t)y*WW + x)*CH))[s16];
            *(uint4*)(dsm + row*OROW_STRIDE + px*OPX_STRIDE + s16*16) = val;
        }
        __syncthreads();

        int miA  = wid >> 2;            // 0..1
        int px0A = (wid & 3) * 16;

        float accA[2][4];
#pragma unroll
        for (int n = 0; n < 2; n++)
#pragma unroll
            for (int e = 0; e < 4; e++) accA[n][e] = 0.f;

#pragma unroll
        for (int k = 0; k < 9; k++){
            int ky = k/3, kx = k - ky*3;
            u32 cHb = smb + ky*OROW_STRIDE + (px0A + lrow + kx)*OPX_STRIDE + lcoff;
            const uint4* wH = oF + (size_t)((k*2 + miA)*8)*32;
#pragma unroll
            for (int ki = 0; ki < 8; ki++){
                uint4 aH = wH[ki*32 + lane];
                u32 bh[4];
                ldmx4(bh, cHb + ki*32);
#pragma unroll
                for (int n = 0; n < 2; n++)
                    mma_f16(accA[n], (const u32*)&aH, bh[2*n], bh[2*n+1]);
            }
        }

        // epilogue -> s_offm[27][64]
        int coA = miA*16 + rfrag;
        int coB = coA + 8;
#pragma unroll
        for (int n = 0; n < 2; n++){
            int px = px0A + n*8 + cfrag;
#pragma unroll
            for (int half = 0; half < 2; half++){
                int co = half ? coB : coA;
                float d0 = half ? accA[n][2] : accA[n][0];
                float d1 = half ? accA[n][3] : accA[n][1];
                if (co < 18){
                    float bb = offb[co];
                    s_offm[co*64 + px]     = d0 + bb;
                    s_offm[co*64 + px + 1] = d1 + bb;
                } else if (co < 27){
                    float bb = modb[co-18];
                    s_offm[co*64 + px]     = 2.f/(1.f + __expf(-(d0 + bb)));
                    s_offm[co*64 + px + 1] = 2.f/(1.f + __expf(-(d1 + bb)));
                }
            }
        }
    }
    __syncthreads();   // patch reads done + s_offm complete; cols may overwrite patch

    // ================= PHASE B: deformable conv =================
    int co0 = (wid >> 1)*32;
    int px0 = (wid & 1)*32;
    int miB = co0 >> 4;

    float acc[2][4][4];
#pragma unroll
    for (int m = 0; m < 2; m++)
#pragma unroll
        for (int n = 0; n < 4; n++)
#pragma unroll
            for (int e = 0; e < 4; e++) acc[m][n][e] = 0.f;

    int   rad0=0, rad1=0, rad2=0, rad3=0;
    float rwt0=0.f, rwt1=0.f, rwt2=0.f, rwt3=0.f;

    auto corners = [&](int k){
        if (lane < 8){
            int pw = wid + lane*8;          // pixel index in tile
            int w  = w0 + pw;
            float oy = s_offm[(2*k  )*64 + pw];
            float ox = s_offm[(2*k+1)*64 + pw];
            float mv = s_offm[(18+k )*64 + pw];
            int ky = k/3, kx = k - ky*3;
            float py  = (float)(h - 1 + ky) + oy;
            float pxf = (float)(w - 1 + kx) + ox;
            float y0f = floorf(py), x0f = floorf(pxf);
            float ay = py - y0f, ax = pxf - x0f;
            int y0 = (int)y0f, x0 = (int)x0f;
#pragma unroll
            for (int j = 0; j < 4; j++){
                int dy = j >> 1, dx = j & 1;
                int yi = y0 + dy, xi = x0 + dx;
                bool ok = ((unsigned)yi < HH) && ((unsigned)xi < WW);
                int yc = min(max(yi, 0), HH-1);
                int xc = min(max(xi, 0), WW-1);
                float wy = dy ? ay : 1.f - ay;
                float wx = dx ? ax : 1.f - ax;
                int   ad = (yc*WW + xc)*CH;
                float wt = ok ? wy*wx*mv : 0.f;
                if (j == 0){ rad0 = ad; rwt0 = wt; }
                else if (j == 1){ rad1 = ad; rwt1 = wt; }
                else if (j == 2){ rad2 = ad; rwt2 = wt; }
                else            { rad3 = ad; rwt3 = wt; }
            }
        }
    };

    auto gather = [&](int buf){
        char* cH = dsm + buf*BUFB;
#pragma unroll
        for (int it = 0; it < 8; it++){
            int a0 = __shfl_sync(0xffffffffu, rad0, it);
            int a1 = __shfl_sync(0xffffffffu, rad1, it);
            int a2 = __shfl_sync(0xffffffffu, rad2, it);
            int a3 = __shfl_sync(0xffffffffu, rad3, it);
            __half2 F0 = __float2half2_rn(__shfl_sync(0xffffffffu, rwt0, it));
            __half2 F1 = __float2half2_rn(__shfl_sync(0xffffffffu, rwt1, it));
            __half2 F2 = __float2half2_rn(__shfl_sync(0xffffffffu, rwt2, it));
            __half2 F3 = __float2half2_rn(__shfl_sync(0xffffffffu, rwt3, it));
            int px = wid + it*8;
            uint2 q0 = ((const uint2*)(srcb + a0))[lane];   // 4 fp16 channels
            uint2 q1 = ((const uint2*)(srcb + a1))[lane];
            uint2 q2 = ((const uint2*)(srcb + a2))[lane];
            uint2 q3 = ((const uint2*)(srcb + a3))[lane];
            // fp16 bilinear blend (HMUL2/HFMA2), no f32 round-trip
            __half2 vLo = __hmul2(*(__half2*)&q0.x, F0);
            __half2 vHi = __hmul2(*(__half2*)&q0.y, F0);
            vLo = __hfma2(*(__half2*)&q1.x, F1, vLo);
            vHi = __hfma2(*(__half2*)&q1.y, F1, vHi);
            vLo = __hfma2(*(__half2*)&q2.x, F2, vLo);
            vHi = __hfma2(*(__half2*)&q2.y, F2, vHi);
            vLo = __hfma2(*(__half2*)&q3.x, F3, vLo);
            vHi = __hfma2(*(__half2*)&q3.y, F3, vHi);
            *(uint2*)(cH + px*ROWB + lane*8) = make_uint2(*(u32*)&vLo, *(u32*)&vHi);
        }
    };

    corners(0);
    gather(0);

    for (int k = 0; k < 9; k++){
        __syncthreads();                 // buf k&1 fully written; prev readers done
        if (k < 8) corners(k+1);
        u32 cHb = smb + (k & 1)*BUFB;
        const uint4* wH = wF + (size_t)(k*8)*8*32;
#pragma unroll
        for (int ki = 0; ki < 8; ki++){
            uint4 aH0 = wH[((miB  )*8 + ki)*32 + lane];
            uint4 aH1 = wH[((miB+1)*8 + ki)*32 + lane];
            u32 adr0 = (u32)((px0 + lrow)*ROWB + ki*32 + lcoff);
            u32 adr1 = adr0 + 16*ROWB;
            u32 bh[8];
            ldmx4(bh    , cHb + adr0);   // n-tiles 0,1
            ldmx4(bh + 4, cHb + adr1);   // n-tiles 2,3
#pragma unroll
            for (int n = 0; n < 4; n++){
                mma_f16(acc[0][n], (const u32*)&aH0, bh[2*n], bh[2*n+1]);
                mma_f16(acc[1][n], (const u32*)&aH1, bh[2*n], bh[2*n+1]);
            }
        }
        if (k < 8) gather((k+1) & 1);
    }

    // ================= epilogue =================
#pragma unroll
    for (int m = 0; m < 2; m++){
        int coA = co0 + m*16 + rfrag;
        int coB = coA + 8;
        if (MODE == 0){
            __half* out = (__half*)out_;
            float aA = p0[coA], aB = p0[coB];
#pragma unroll
            for (int n = 0; n < 4; n++){
                int px = px0 + n*8 + cfrag;
                size_t base = (((size_t)b*HWP) + h*WW + w0 + px)*CH;   // NHWC
                float d0 = acc[m][n][0], d1 = acc[m][n][1];
                float d2 = acc[m][n][2], d3 = acc[m][n][3];
                out[base + coA]      = __float2half(d0 > 0.f ? d0 : aA*d0);
                out[base + CH + coA] = __float2half(d1 > 0.f ? d1 : aA*d1);
                out[base + coB]      = __float2half(d2 > 0.f ? d2 : aB*d2);
                out[base + CH + coB] = __float2half(d3 > 0.f ? d3 : aB*d3);
            }
        } else {
            float* out = (float*)out_;
            float sA  = bn_g[coA] * rsqrtf(bn_v[coA] + 1e-5f);
            float bA  = bn_b[coA] - bn_m[coA]*sA;
            float sB  = bn_g[coB] * rsqrtf(bn_v[coB] + 1e-5f);
            float bB  = bn_b[coB] - bn_m[coB]*sB;
#pragma unroll
            for (int n = 0; n < 4; n++){
                int px = px0 + n*8 + cfrag;
                size_t baseA = ((size_t)(b*CH + coA))*HWP + (size_t)h*WW + w0 + px;
                size_t baseB = baseA + (size_t)8*HWP;
                float2 xA = *(const float2*)(p0 + baseA);
                float2 xB = *(const float2*)(p0 + baseB);
                float d0 = acc[m][n][0], d1 = acc[m][n][1];
                float d2 = acc[m][n][2], d3 = acc[m][n][3];
                *(float2*)(out + baseA) = make_float2(d0*sA + bA + xA.x, d1*sA + bA + xA.y);
                *(float2*)(out + baseB) = make_float2(d2*sB + bB + xB.x, d3*sB + bB + xB.y);
            }
        }
    }
}

// ================= host launcher =================
extern "C" void kernel_launch(void* const* d_in, const int* in_sizes, int n_in,
                              void* d_out, int out_size){
    const float* x      = (const float*)d_in[0];
    const float* bn1_g  = (const float*)d_in[1];
    const float* bn1_b  = (const float*)d_in[2];
    const float* bn1_m  = (const float*)d_in[3];
    const float* bn1_v  = (const float*)d_in[4];
    const float* off1_w = (const float*)d_in[5];
    const float* off1_b = (const float*)d_in[6];
    const float* mod1_w = (const float*)d_in[7];
    const float* mod1_b = (const float*)d_in[8];
    const float* w1     = (const float*)d_in[9];
    const float* alpha  = (const float*)d_in[10];
    const float* off2_w = (const float*)d_in[11];
    const float* off2_b = (const float*)d_in[12];
    const float* mod2_w = (const float*)d_in[13];
    const float* mod2_b = (const float*)d_in[14];
    const float* w2     = (const float*)d_in[15];
    const float* bn2_g  = (const float*)d_in[16];
    const float* bn2_b  = (const float*)d_in[17];
    const float* bn2_m  = (const float*)d_in[18];
    const float* bn2_v  = (const float*)d_in[19];
    float* out = (float*)d_out;

    __half *r1p, *d1p;
    uint4 *wf1, *wf2, *of1, *of2;
    cudaGetSymbolAddress((void**)&r1p, g_r1);
    cudaGetSymbolAddress((void**)&d1p, g_d1);
    cudaGetSymbolAddress((void**)&wf1, g_wF1);
    cudaGetSymbolAddress((void**)&wf2, g_wF2);
    cudaGetSymbolAddress((void**)&of1, g_oF1);
    cudaGetSymbolAddress((void**)&of2, g_oF2);

    cudaFuncSetAttribute(fused_layer_kernel<0>, cudaFuncAttributeMaxDynamicSharedMemorySize, FUSED_SMEM);
    cudaFuncSetAttribute(fused_layer_kernel<1>, cudaFuncAttributeMaxDynamicSharedMemorySize, FUSED_SMEM);

    // 1) weight prep (all fragments, one launch)
    prep_all_kernel<<<(36864 + 9216 + 255)/256, 256>>>(w1, w2, off1_w, mod1_w, off2_w, mod2_w);
    // 2) bn1 -> NHWC fp16 r1
    bn1_nhwc_kernel<<<8192, 256>>>(x, bn1_g, bn1_b, bn1_m, bn1_v);
    // 3) fused layer 1: offmod + deform (+prelu) -> NHWC fp16 d1
    fused_layer_kernel<0><<<1024, 256, FUSED_SMEM>>>(r1p, of1, off1_b, mod1_b, wf1, alpha,
                                                     nullptr, nullptr, nullptr, nullptr, d1p);
    // 4) fused layer 2: offmod + deform (+bn2 +shortcut) -> CHW fp32 out
    fused_layer_kernel<1><<<1024, 256, FUSED_SMEM>>>(d1p, of2, off2_b, mod2_b, wf2, x,
                                                     bn2_g, bn2_b, bn2_m, bn2_v, out);
}

// round 17
// speedup vs baseline: 1.4464x; 1.4464x over previous
#include <cuda_runtime.h>
#include <cuda_fp16.h>
#include <math.h>
#include <cstdint>

#define BSZ 4
#define CH  128
#define HH  128
#define WW  128
#define HWP (HH*WW)

typedef unsigned long long u64;
typedef uint32_t u32;

// ================= scratch (static device memory) =================
__device__ __half g_r1 [(size_t)BSZ*HWP*CH];  // bn1 output, NHWC fp16
__device__ __half g_d1 [(size_t)BSZ*HWP*CH];  // layer1 output, NHWC fp16
// deform weights, fragment-packed fp16: [k][mi 8][ki 8][lane 32] uint4
__device__ uint4 g_wF1[9*8*8*32];
__device__ uint4 g_wF2[9*8*8*32];
// offmod weights (27 rows padded to 32): [k][mi 2][ki 8][lane 32] uint4
__device__ uint4 g_oF1[9*2*8*32];
__device__ uint4 g_oF2[9*2*8*32];

// ================= helpers =================
__device__ __forceinline__ u32 smem_to_u32(const void* p){
    u32 a; asm("{ .reg .u64 t; cvta.to.shared.u64 t, %1; cvt.u32.u64 %0, t; }" : "=r"(a) : "l"(p));
    return a;
}
__device__ __forceinline__ u32 pack_h2(float a, float b){
    __half2 h = __floats2half2_rn(a, b);
    return *(u32*)&h;
}
__device__ __forceinline__ void mma_f16(float* d, const u32* a, u32 b0, u32 b1){
    asm volatile(
        "mma.sync.aligned.m16n8k16.row.col.f32.f16.f16.f32 "
        "{%0,%1,%2,%3}, {%4,%5,%6,%7}, {%8,%9}, {%0,%1,%2,%3};"
        : "+f"(d[0]), "+f"(d[1]), "+f"(d[2]), "+f"(d[3])
        : "r"(a[0]), "r"(a[1]), "r"(a[2]), "r"(a[3]), "r"(b0), "r"(b1));
}
// non-trans: cols smem is px-major (already B^T) -> direct col-major B fragment
__device__ __forceinline__ void ldmx4(u32* r, u32 addr){
    asm volatile("ldmatrix.sync.aligned.m8n8.x4.shared.b16 {%0,%1,%2,%3}, [%4];"
        : "=r"(r[0]), "=r"(r[1]), "=r"(r[2]), "=r"(r[3]) : "r"(addr));
}

#define ROWB 272
#define BUFB (64*ROWB)        // 17408 bytes per cols buffer (fp16)

// phase-A patch: [row 3][px 66][272B] fp16
#define OPX_STRIDE 272
#define OROW_STRIDE (66*OPX_STRIDE)      // 17952
#define OPATCH_BYTES (3*OROW_STRIDE)     // 53856
// s_offm lives above the union of (patch, cols double buffer)
#define SOFFM_OFF 53856                   // 27*64 floats = 6912 B
#define FUSED_SMEM (SOFFM_OFF + 6912)     // 60768

// ================= prep: all weights -> fragment order, fp16 ================
__global__ void prep_all_kernel(const float* __restrict__ w1, const float* __restrict__ w2,
                                const float* __restrict__ o1w, const float* __restrict__ m1w,
                                const float* __restrict__ o2w, const float* __restrict__ m2w){
    int i = blockIdx.x*256 + threadIdx.x;
    if (i < 36864){
        int lane = i & 31;
        int ki   = (i>>5) & 7;
        int mi   = (i>>8) & 7;
        int rest = i >> 11;            // 0..17
        int k    = rest % 9;
        int layer= rest / 9;
        const float* w = layer ? w2 : w1;
        int r  = lane >> 2;
        int cp = (lane & 3)*2;
        int row0 = mi*16 + r;
        int col0 = ki*16 + cp;
        float v[4][2];
#pragma unroll
        for (int q = 0; q < 4; q++){
            int ro = row0 + ((q & 1) ? 8 : 0);
            int co_ = col0 + ((q >> 1) ? 8 : 0);
#pragma unroll
            for (int e = 0; e < 2; e++)
                v[q][e] = w[(ro*CH + (co_+e))*9 + k];
        }
        uint4 o;
        o.x = pack_h2(v[0][0], v[0][1]);
        o.y = pack_h2(v[1][0], v[1][1]);
        o.z = pack_h2(v[2][0], v[2][1]);
        o.w = pack_h2(v[3][0], v[3][1]);
        uint4* dst = layer ? g_wF2 : g_wF1;
        dst[((k*8 + mi)*8 + ki)*32 + lane] = o;
    } else if (i < 36864 + 9216){
        int j = i - 36864;
        int lane = j & 31;
        int ki   = (j>>5) & 7;
        int mi   = (j>>8) & 1;
        int rest = j >> 9;             // 0..17
        int k    = rest % 9;
        int layer= rest / 9;
        const float* ow = layer ? o2w : o1w;
        const float* mw = layer ? m2w : m1w;
        int r  = lane >> 2;
        int cp = (lane & 3)*2;
        int row0 = mi*16 + r;
        int col0 = ki*16 + cp;
        float v[4][2];
#pragma unroll
        for (int q = 0; q < 4; q++){
            int ro = row0 + ((q & 1) ? 8 : 0);
            int c_ = col0 + ((q >> 1) ? 8 : 0);
#pragma unroll
            for (int e = 0; e < 2; e++){
                int c = c_ + e;
                float val = 0.f;
                if (ro < 18)      val = ow[(ro*CH + c)*9 + k];
                else if (ro < 27) val = mw[((ro-18)*CH + c)*9 + k];
                v[q][e] = val;
            }
        }
        uint4 o;
        o.x = pack_h2(v[0][0], v[0][1]);
        o.y = pack_h2(v[1][0], v[1][1]);
        o.z = pack_h2(v[2][0], v[2][1]);
        o.w = pack_h2(v[3][0], v[3][1]);
        uint4* dst = layer ? g_oF2 : g_oF1;
        dst[((k*2 + mi)*8 + ki)*32 + lane] = o;
    }
}

// ================= bn1 + transpose to NHWC fp16 =================
__global__ void bn1_nhwc_kernel(const float* __restrict__ x,
                                const float* __restrict__ g, const float* __restrict__ b_,
                                const float* __restrict__ m, const float* __restrict__ v){
    __shared__ float tile[32][33];
    int bid = blockIdx.x;
    int wb = bid & 3, cb = (bid >> 2) & 3, h = (bid >> 4) & 127, b = bid >> 11;
    int tx = threadIdx.x & 31, ty = threadIdx.x >> 5;
    int c0 = cb*32, w0 = wb*32;
#pragma unroll
    for (int i = 0; i < 4; i++){
        int c = c0 + ty + i*8;
        float s  = g[c] * rsqrtf(v[c] + 1e-5f);
        float bb = b_[c] - m[c]*s;
        float xv = x[((size_t)(b*CH + c))*HWP + h*WW + w0 + tx];
        tile[ty + i*8][tx] = xv*s + bb;
    }
    __syncthreads();
#pragma unroll
    for (int i = 0; i < 4; i++){
        int w = w0 + ty + i*8;
        g_r1[(((size_t)b*HWP) + h*WW + w)*CH + c0 + tx] = __float2half(tile[tx][ty + i*8]);
    }
}

// ================= fused offmod + deformable conv =================
// grid 1024 = b*h*2half; block 256 (8 warps); tile 64px x 128co.
// Phase A: dense 3x3 conv (27 ch) on the 3x66 patch -> s_offm[27][64] in smem.
// Phase B: deformable conv, corners from s_offm (fp32 blend — R16 showed the
// half2 blend halves ILP on the latency-critical gather and regresses 40%).
// MODE 0: out = prelu(conv) -> NHWC fp16 d1 (p0 = alpha)
// MODE 1: out = bn2(conv) + x -> CHW fp32 d_out (p0 = x CHW)
template<int MODE>
__global__ void __launch_bounds__(256,2)
fused_layer_kernel(const __half* __restrict__ src,
                   const uint4* __restrict__ oF,
                   const float* __restrict__ offb, const float* __restrict__ modb,
                   const uint4* __restrict__ wF,
                   const float* __restrict__ p0,
                   const float* __restrict__ bn_g, const float* __restrict__ bn_b,
                   const float* __restrict__ bn_m, const float* __restrict__ bn_v,
                   void* __restrict__ out_){
    extern __shared__ __align__(16) char dsm[];
    float* s_offm = (float*)(dsm + SOFFM_OFF);   // [27][64]

    int t = threadIdx.x, lane = t & 31, wid = t >> 5;
    int b = blockIdx.x >> 8, rem = blockIdx.x & 255;
    int h = rem >> 1, w0 = (rem & 1) << 6;

    int sub  = lane & 7;
    int grp  = lane >> 3;
    int lrow = ((grp >> 1) << 3) + sub;
    int lcoff= (grp & 1) << 4;
    int rfrag = lane >> 2;
    int cfrag = (lane & 3)*2;

    u32 smb = smem_to_u32(dsm);
    const __half* srcb = src + (size_t)b*HWP*CH;

    // ================= PHASE A: offset/mask conv =================
    {
        // copy 3x66 fp16 patch
        for (int i = t; i < 198*16; i += 256){
            int pair = i >> 4;
            int s16  = i & 15;
            int row  = pair / 66;
            int px   = pair - row*66;
            int y = h - 1 + row;
            int x = w0 - 1 + px;
            bool ok = ((unsigned)y < HH) && ((unsigned)x < WW);
            uint4 val = make_uint4(0,0,0,0);
            if (ok) val = ((const uint4*)(srcb + ((size_t)y*WW + x)*CH))[s16];
            *(uint4*)(dsm + row*OROW_STRIDE + px*OPX_STRIDE + s16*16) = val;
        }
        __syncthreads();

        int miA  = wid >> 2;            // 0..1
        int px0A = (wid & 3) * 16;

        float accA[2][4];
#pragma unroll
        for (int n = 0; n < 2; n++)
#pragma unroll
            for (int e = 0; e < 4; e++) accA[n][e] = 0.f;

#pragma unroll
        for (int k = 0; k < 9; k++){
            int ky = k/3, kx = k - ky*3;
            u32 cHb = smb + ky*OROW_STRIDE + (px0A + lrow + kx)*OPX_STRIDE + lcoff;
            const uint4* wH = oF + (size_t)((k*2 + miA)*8)*32;
#pragma unroll
            for (int ki = 0; ki < 8; ki++){
                uint4 aH = wH[ki*32 + lane];
                u32 bh[4];
                ldmx4(bh, cHb + ki*32);
#pragma unroll
                for (int n = 0; n < 2; n++)
                    mma_f16(accA[n], (const u32*)&aH, bh[2*n], bh[2*n+1]);
            }
        }

        // epilogue -> s_offm[27][64]
        int coA = miA*16 + rfrag;
        int coB = coA + 8;
#pragma unroll
        for (int n = 0; n < 2; n++){
            int px = px0A + n*8 + cfrag;
#pragma unroll
            for (int half = 0; half < 2; half++){
                int co = half ? coB : coA;
                float d0 = half ? accA[n][2] : accA[n][0];
                float d1 = half ? accA[n][3] : accA[n][1];
                if (co < 18){
                    float bb = offb[co];
                    s_offm[co*64 + px]     = d0 + bb;
                    s_offm[co*64 + px + 1] = d1 + bb;
                } else if (co < 27){
                    float bb = modb[co-18];
                    s_offm[co*64 + px]     = 2.f/(1.f + __expf(-(d0 + bb)));
                    s_offm[co*64 + px + 1] = 2.f/(1.f + __expf(-(d1 + bb)));
                }
            }
        }
    }
    __syncthreads();   // patch reads done + s_offm complete; cols may overwrite patch

    // ================= PHASE B: deformable conv =================
    int co0 = (wid >> 1)*32;
    int px0 = (wid & 1)*32;
    int miB = co0 >> 4;

    float acc[2][4][4];
#pragma unroll
    for (int m = 0; m < 2; m++)
#pragma unroll
        for (int n = 0; n < 4; n++)
#pragma unroll
            for (int e = 0; e < 4; e++) acc[m][n][e] = 0.f;

    int   rad0=0, rad1=0, rad2=0, rad3=0;
    float rwt0=0.f, rwt1=0.f, rwt2=0.f, rwt3=0.f;

    auto corners = [&](int k){
        if (lane < 8){
            int pw = wid + lane*8;          // pixel index in tile
            int w  = w0 + pw;
            float oy = s_offm[(2*k  )*64 + pw];
            float ox = s_offm[(2*k+1)*64 + pw];
            float mv = s_offm[(18+k )*64 + pw];
            int ky = k/3, kx = k - ky*3;
            float py  = (float)(h - 1 + ky) + oy;
            float pxf = (float)(w - 1 + kx) + ox;
            float y0f = floorf(py), x0f = floorf(pxf);
            float ay = py - y0f, ax = pxf - x0f;
            int y0 = (int)y0f, x0 = (int)x0f;
#pragma unroll
            for (int j = 0; j < 4; j++){
                int dy = j >> 1, dx = j & 1;
                int yi = y0 + dy, xi = x0 + dx;
                bool ok = ((unsigned)yi < HH) && ((unsigned)xi < WW);
                int yc = min(max(yi, 0), HH-1);
                int xc = min(max(xi, 0), WW-1);
                float wy = dy ? ay : 1.f - ay;
                float wx = dx ? ax : 1.f - ax;
                int   ad = (yc*WW + xc)*CH;
                float wt = ok ? wy*wx*mv : 0.f;
                if (j == 0){ rad0 = ad; rwt0 = wt; }
                else if (j == 1){ rad1 = ad; rwt1 = wt; }
                else if (j == 2){ rad2 = ad; rwt2 = wt; }
                else            { rad3 = ad; rwt3 = wt; }
            }
        }
    };

    auto blend4 = [&](uint2 r, float f, float4 &v){
        float2 a = __half22float2(*(__half2*)&r.x);
        float2 c = __half22float2(*(__half2*)&r.y);
        v.x += f*a.x; v.y += f*a.y; v.z += f*c.x; v.w += f*c.y;
    };

    auto gather = [&](int buf){
        char* cH = dsm + buf*BUFB;
#pragma unroll
        for (int it = 0; it < 8; it++){
            int a0 = __shfl_sync(0xffffffffu, rad0, it);
            int a1 = __shfl_sync(0xffffffffu, rad1, it);
            int a2 = __shfl_sync(0xffffffffu, rad2, it);
            int a3 = __shfl_sync(0xffffffffu, rad3, it);
            float f0 = __shfl_sync(0xffffffffu, rwt0, it);
            float f1 = __shfl_sync(0xffffffffu, rwt1, it);
            float f2 = __shfl_sync(0xffffffffu, rwt2, it);
            float f3 = __shfl_sync(0xffffffffu, rwt3, it);
            int px = wid + it*8;
            uint2 q0 = ((const uint2*)(srcb + a0))[lane];   // 4 fp16 channels
            uint2 q1 = ((const uint2*)(srcb + a1))[lane];
            uint2 q2 = ((const uint2*)(srcb + a2))[lane];
            uint2 q3 = ((const uint2*)(srcb + a3))[lane];
            float4 vv = make_float4(0.f,0.f,0.f,0.f);
            blend4(q0, f0, vv);
            blend4(q1, f1, vv);
            blend4(q2, f2, vv);
            blend4(q3, f3, vv);
            *(uint2*)(cH + px*ROWB + lane*8) =
                make_uint2(pack_h2(vv.x, vv.y), pack_h2(vv.z, vv.w));
        }
    };

    corners(0);
    gather(0);

    for (int k = 0; k < 9; k++){
        __syncthreads();                 // buf k&1 fully written; prev readers done
        if (k < 8) corners(k+1);
        u32 cHb = smb + (k & 1)*BUFB;
        const uint4* wH = wF + (size_t)(k*8)*8*32;
#pragma unroll
        for (int ki = 0; ki < 8; ki++){
            uint4 aH0 = wH[((miB  )*8 + ki)*32 + lane];
            uint4 aH1 = wH[((miB+1)*8 + ki)*32 + lane];
            u32 adr0 = (u32)((px0 + lrow)*ROWB + ki*32 + lcoff);
            u32 adr1 = adr0 + 16*ROWB;
            u32 bh[8];
            ldmx4(bh    , cHb + adr0);   // n-tiles 0,1
            ldmx4(bh + 4, cHb + adr1);   // n-tiles 2,3
#pragma unroll
            for (int n = 0; n < 4; n++){
                mma_f16(acc[0][n], (const u32*)&aH0, bh[2*n], bh[2*n+1]);
                mma_f16(acc[1][n], (const u32*)&aH1, bh[2*n], bh[2*n+1]);
            }
        }
        if (k < 8) gather((k+1) & 1);
    }

    // ================= epilogue =================
#pragma unroll
    for (int m = 0; m < 2; m++){
        int coA = co0 + m*16 + rfrag;
        int coB = coA + 8;
        if (MODE == 0){
            __half* out = (__half*)out_;
            float aA = p0[coA], aB = p0[coB];
#pragma unroll
            for (int n = 0; n < 4; n++){
                int px = px0 + n*8 + cfrag;
                size_t base = (((size_t)b*HWP) + h*WW + w0 + px)*CH;   // NHWC
                float d0 = acc[m][n][0], d1 = acc[m][n][1];
                float d2 = acc[m][n][2], d3 = acc[m][n][3];
                out[base + coA]      = __float2half(d0 > 0.f ? d0 : aA*d0);
                out[base + CH + coA] = __float2half(d1 > 0.f ? d1 : aA*d1);
                out[base + coB]      = __float2half(d2 > 0.f ? d2 : aB*d2);
                out[base + CH + coB] = __float2half(d3 > 0.f ? d3 : aB*d3);
            }
        } else {
            float* out = (float*)out_;
            float sA  = bn_g[coA] * rsqrtf(bn_v[coA] + 1e-5f);
            float bA  = bn_b[coA] - bn_m[coA]*sA;
            float sB  = bn_g[coB] * rsqrtf(bn_v[coB] + 1e-5f);
            float bB  = bn_b[coB] - bn_m[coB]*sB;
#pragma unroll
            for (int n = 0; n < 4; n++){
                int px = px0 + n*8 + cfrag;
                size_t baseA = ((size_t)(b*CH + coA))*HWP + (size_t)h*WW + w0 + px;
                size_t baseB = baseA + (size_t)8*HWP;
                float2 xA = *(const float2*)(p0 + baseA);
                float2 xB = *(const float2*)(p0 + baseB);
                float d0 = acc[m][n][0], d1 = acc[m][n][1];
                float d2 = acc[m][n][2], d3 = acc[m][n][3];
                *(float2*)(out + baseA) = make_float2(d0*sA + bA + xA.x, d1*sA + bA + xA.y);
                *(float2*)(out + baseB) = make_float2(d2*sB + bB + xB.x, d3*sB + bB + xB.y);
            }
        }
    }
}

// ================= host launcher =================
extern "C" void kernel_launch(void* const* d_in, const int* in_sizes, int n_in,
                              void* d_out, int out_size){
    const float* x      = (const float*)d_in[0];
    const float* bn1_g  = (const float*)d_in[1];
    const float* bn1_b  = (const float*)d_in[2];
    const float* bn1_m  = (const float*)d_in[3];
    const float* bn1_v  = (const float*)d_in[4];
    const float* off1_w = (const float*)d_in[5];
    const float* off1_b = (const float*)d_in[6];
    const float* mod1_w = (const float*)d_in[7];
    const float* mod1_b = (const float*)d_in[8];
    const float* w1     = (const float*)d_in[9];
    const float* alpha  = (const float*)d_in[10];
    const float* off2_w = (const float*)d_in[11];
    const float* off2_b = (const float*)d_in[12];
    const float* mod2_w = (const float*)d_in[13];
    const float* mod2_b = (const float*)d_in[14];
    const float* w2     = (const float*)d_in[15];
    const float* bn2_g  = (const float*)d_in[16];
    const float* bn2_b  = (const float*)d_in[17];
    const float* bn2_m  = (const float*)d_in[18];
    const float* bn2_v  = (const float*)d_in[19];
    float* out = (float*)d_out;

    __half *r1p, *d1p;
    uint4 *wf1, *wf2, *of1, *of2;
    cudaGetSymbolAddress((void**)&r1p, g_r1);
    cudaGetSymbolAddress((void**)&d1p, g_d1);
    cudaGetSymbolAddress((void**)&wf1, g_wF1);
    cudaGetSymbolAddress((void**)&wf2, g_wF2);
    cudaGetSymbolAddress((void**)&of1, g_oF1);
    cudaGetSymbolAddress((void**)&of2, g_oF2);

    cudaFuncSetAttribute(fused_layer_kernel<0>, cudaFuncAttributeMaxDynamicSharedMemorySize, FUSED_SMEM);
    cudaFuncSetAttribute(fused_layer_kernel<1>, cudaFuncAttributeMaxDynamicSharedMemorySize, FUSED_SMEM);

    // 1) weight prep (all fragments, one launch)
    prep_all_kernel<<<(36864 + 9216 + 255)/256, 256>>>(w1, w2, off1_w, mod1_w, off2_w, mod2_w);
    // 2) bn1 -> NHWC fp16 r1
    bn1_nhwc_kernel<<<8192, 256>>>(x, bn1_g, bn1_b, bn1_m, bn1_v);
    // 3) fused layer 1: offmod + deform (+prelu) -> NHWC fp16 d1
    fused_layer_kernel<0><<<1024, 256, FUSED_SMEM>>>(r1p, of1, off1_b, mod1_b, wf1, alpha,
                                                     nullptr, nullptr, nullptr, nullptr, d1p);
    // 4) fused layer 2: offmod + deform (+bn2 +shortcut) -> CHW fp32 out
    fused_layer_kernel<1><<<1024, 256, FUSED_SMEM>>>(d1p, of2, off2_b, mod2_b, wf2, x,
                                                     bn2_g, bn2_b, bn2_m, bn2_v, out);
}